// round 14
// baseline (speedup 1.0000x reference)
#include <cuda_runtime.h>
#include <cstdint>

#define HIDDEN  4096
#define RANK    16
#define ROWS    4
#define THREADS 256
#define NWARP   8
#define TOTAL_ROWS 16384
#define TWO_OVER_PI 0.63661977236758134f

typedef unsigned long long ull;

// Dequantized weights in device scratch (no allocations).
// g_Aft[r*HIDDEN+k] = A[k][r] * sA[r] * 2/pi   (transposed, coalesced loads)
// g_Bf [r*HIDDEN+c] = B[r][c] * sB[c]
__device__ float g_Aft[RANK * HIDDEN];
__device__ float g_Bf[RANK * HIDDEN];

// --- storage-format probe (validated R4+) ---
__device__ __forceinline__ int detect_mode(const void* p) {
    const unsigned* w = (const unsigned*)p;
    int vi = 0, vf = 0;
    #pragma unroll
    for (int i = 0; i < 32; i++) {
        unsigned u = w[i];
        int s = (int)u;
        if (s >= -127 && s <= 127) vi++;
        unsigned exp = (u >> 23) & 0xffu;
        if ((u & 0x7fffffffu) == 0u || (exp >= 127u && exp <= 133u)) vf++;
    }
    if (vi >= 24) return 1;
    if (vf >= 24) return 0;
    return 2;
}
__device__ __forceinline__ float load_elem(const void* p, int mode, int i) {
    if (mode == 1) return (float)((const int*)p)[i];
    if (mode == 0) return ((const float*)p)[i];
    return (float)((const signed char*)p)[i];
}

__global__ void prep_kernel(const void* __restrict__ A, const void* __restrict__ B,
                            const float* __restrict__ sA, const float* __restrict__ sB)
{
    __shared__ int mA, mB;
    if (threadIdx.x == 0) { mA = detect_mode(A); mB = detect_mode(B); }
    __syncthreads();
    const int i = blockIdx.x * blockDim.x + threadIdx.x;    // 65536 threads
    {
        const int k = i >> 4, r = i & 15;
        g_Aft[(size_t)r * HIDDEN + k] = load_elem(A, mA, i) * sA[r] * TWO_OVER_PI;
    }
    g_Bf[i] = load_elem(B, mB, i) * sB[i & (HIDDEN - 1)];
}

// ---- packed f32x2 primitives ----
__device__ __forceinline__ ull pack2(float a, float b) {
    ull d; asm("mov.b64 %0, {%1, %2};" : "=l"(d) : "f"(a), "f"(b)); return d;
}
__device__ __forceinline__ ull dup2(float a) { return pack2(a, a); }
__device__ __forceinline__ ull fma2(ull a, ull b, ull c) {
    ull d; asm("fma.rn.f32x2 %0, %1, %2, %3;" : "=l"(d) : "l"(a), "l"(b), "l"(c)); return d;
}
__device__ __forceinline__ ull mul2(ull a, ull b) {
    ull d; asm("mul.rn.f32x2 %0, %1, %2;" : "=l"(d) : "l"(a), "l"(b)); return d;
}
__device__ __forceinline__ ull add2(ull a, ull b) {
    ull d; asm("add.rn.f32x2 %0, %1, %2;" : "=l"(d) : "l"(a), "l"(b)); return d;
}

union F4U2 { float4 f4; ull u[2]; };

// Packed 2-wide sin: magic-number rint (q and its parity, no CVT/MUFU),
// same Cody-Waite constants + degree-9 odd minimax poly as the scalar path.
__device__ __forceinline__ ull sin2(ull t) {
    const ull INVPI  = dup2(0.3183098861837907f);
    const ull MAGIC  = dup2(12582912.0f);            // 1.5 * 2^23
    const ull NMAGIC = dup2(-12582912.0f);
    const ull NPIHI  = dup2(-3.14159274101257f);
    const ull PILO   = dup2(8.742277657e-8f);
    ull m  = fma2(t, INVPI, MAGIC);                  // q in low mantissa bits
    ull qf = add2(m, NMAGIC);                        // q as float
    ull r  = fma2(qf, NPIHI, t);
    r = fma2(qf, PILO, r);                           // r = t - q*pi
    // parity of q = mantissa bit0 of m; fold sign into r (sin is odd)
    unsigned mlo = (unsigned)m, mhi = (unsigned)(m >> 32);
    ull sign = (((ull)(mhi << 31)) << 32) | (ull)(mlo << 31);
    r ^= sign;
    ull s = mul2(r, r);
    ull p = dup2(2.86567956e-6f);
    p = fma2(p, s, dup2(-1.98559923e-4f));
    p = fma2(p, s, dup2(8.33338592e-3f));
    p = fma2(p, s, dup2(-1.66666672e-1f));
    return fma2(p, mul2(r, s), r);
}

__global__ __launch_bounds__(THREADS, 2)          // 2 CTAs/SM
void pilora_kernel(const float* __restrict__ x, float* __restrict__ y)
{
    extern __shared__ float xs[];                 // [ROWS][HIDDEN]  64 KB
    __shared__ float red[NWARP][ROWS * RANK];
    __shared__ ull hs2[ROWS * RANK];              // h duplicated into both halves

    const int tid  = threadIdx.x;
    const int lane = tid & 31;
    const int w    = tid >> 5;
    const size_t rowbase = (size_t)blockIdx.x * ROWS;

    // ---- phase 1 (fused staging, scalar FMA — unchanged from R13) ----
    float acc[ROWS][RANK];
    #pragma unroll
    for (int rr = 0; rr < ROWS; rr++)
        #pragma unroll
        for (int r = 0; r < RANK; r++)
            acc[rr][r] = 0.0f;

    #pragma unroll
    for (int i = 0; i < 4; i++) {
        const int k0 = w * 512 + i * 128 + lane * 4;

        float4 xv[ROWS];
        #pragma unroll
        for (int rr = 0; rr < ROWS; rr++) {
            xv[rr] = *(const float4*)(x + (rowbase + rr) * HIDDEN + k0);
            *(float4*)(xs + rr * HIDDEN + k0) = xv[rr];
        }

        #pragma unroll
        for (int rc = 0; rc < 4; rc++) {
            float4 av[4];
            #pragma unroll
            for (int c = 0; c < 4; c++)
                av[c] = *(const float4*)(g_Aft + (size_t)(rc * 4 + c) * HIDDEN + k0);
            #pragma unroll
            for (int c = 0; c < 4; c++) {
                const int r = rc * 4 + c;
                #pragma unroll
                for (int rr = 0; rr < ROWS; rr++) {
                    float t = acc[rr][r];
                    t = fmaf(xv[rr].x, av[c].x, t);
                    t = fmaf(xv[rr].y, av[c].y, t);
                    t = fmaf(xv[rr].z, av[c].z, t);
                    t = fmaf(xv[rr].w, av[c].w, t);
                    acc[rr][r] = t;
                }
            }
        }
    }

    // warp butterfly reduction; lane 0 stores per-warp partials
    #pragma unroll
    for (int rr = 0; rr < ROWS; rr++) {
        #pragma unroll
        for (int r = 0; r < RANK; r++) {
            float v = acc[rr][r];
            v += __shfl_xor_sync(0xffffffffu, v, 16);
            v += __shfl_xor_sync(0xffffffffu, v, 8);
            v += __shfl_xor_sync(0xffffffffu, v, 4);
            v += __shfl_xor_sync(0xffffffffu, v, 2);
            v += __shfl_xor_sync(0xffffffffu, v, 1);
            if (lane == 0) red[w][rr * RANK + r] = v;
        }
    }
    __syncthreads();

    if (tid < ROWS * RANK) {
        float h = 0.0f;
        #pragma unroll
        for (int ww = 0; ww < NWARP; ww++) h += red[ww][tid];
        hs2[tid] = dup2(h);                // pre-duplicated for packed phase 2
    }
    __syncthreads();

    // ---- phase 2 (PACKED f32x2): y = x + 2*sin( sum_r h*Bf ) ----
    #pragma unroll
    for (int i = 0; i < 4; i++) {
        const int c0 = w * 512 + i * 128 + lane * 4;

        ull acc2[ROWS][2];
        #pragma unroll
        for (int rr = 0; rr < ROWS; rr++) { acc2[rr][0] = 0ull; acc2[rr][1] = 0ull; }

        // rank-chunked B loads: 4 independent LDG.128, then 32 FMA2
        #pragma unroll
        for (int rc = 0; rc < 4; rc++) {
            F4U2 bv[4];
            #pragma unroll
            for (int c = 0; c < 4; c++)
                bv[c].f4 = *(const float4*)(g_Bf + (size_t)(rc * 4 + c) * HIDDEN + c0);
            #pragma unroll
            for (int c = 0; c < 4; c++) {
                const int r = rc * 4 + c;
                #pragma unroll
                for (int rr = 0; rr < ROWS; rr++) {
                    const ull hh = hs2[rr * RANK + r];    // LDS.64 broadcast
                    acc2[rr][0] = fma2(hh, bv[c].u[0], acc2[rr][0]);
                    acc2[rr][1] = fma2(hh, bv[c].u[1], acc2[rr][1]);
                }
            }
        }

        const ull TWO2 = dup2(2.0f);
        #pragma unroll
        for (int rr = 0; rr < ROWS; rr++) {
            F4U2 xv; xv.f4 = *(const float4*)(xs + rr * HIDDEN + c0);
            F4U2 ov;
            ov.u[0] = fma2(TWO2, sin2(acc2[rr][0]), xv.u[0]);
            ov.u[1] = fma2(TWO2, sin2(acc2[rr][1]), xv.u[1]);
            *(float4*)(y + (rowbase + rr) * HIDDEN + c0) = ov.f4;
        }
    }
}

extern "C" void kernel_launch(void* const* d_in, const int* in_sizes, int n_in,
                              void* d_out, int out_size)
{
    // Rank-order binding by size (robust; validated since R4)
    int idx[16];
    const int m = (n_in < 16) ? n_in : 16;
    for (int i = 0; i < m; i++) idx[i] = i;
    for (int i = 0; i < m; i++) {
        int best = i;
        for (int j = i + 1; j < m; j++)
            if (in_sizes[idx[j]] < in_sizes[idx[best]]) best = j;
        if (best != i) {
            int t = idx[best];
            for (int j = best; j > i; j--) idx[j] = idx[j - 1];
            idx[i] = t;
        }
    }
    const float* sA = (const float*)d_in[idx[0]];
    const float* sB = (const float*)d_in[idx[1]];
    const void*  A  = d_in[idx[2]];
    const void*  B  = d_in[idx[3]];
    const float* x  = (const float*)d_in[idx[m - 1]];
    float* y = (float*)d_out;

    prep_kernel<<<(HIDDEN * RANK) / 256, 256>>>(A, B, sA, sB);

    const size_t smem = (size_t)ROWS * HIDDEN * sizeof(float);   // 64 KB
    cudaFuncSetAttribute(pilora_kernel,
                         cudaFuncAttributeMaxDynamicSharedMemorySize, (int)smem);
    pilora_kernel<<<TOTAL_ROWS / ROWS, THREADS, smem>>>(x, y);
}

// round 15
// speedup vs baseline: 1.2121x; 1.2121x over previous
#include <cuda_runtime.h>
#include <cstdint>

#define HIDDEN  4096
#define RANK    16
#define ROWS    8
#define THREADS 512
#define NWARP   16
#define TOTAL_ROWS 16384
#define TWO_OVER_PI 0.63661977236758134f

// Dequantized weights in device scratch (no allocations).
// g_Aft[r*HIDDEN+k] = A[k][r] * sA[r] * 2/pi   (transposed, coalesced loads)
// g_Bf [r*HIDDEN+c] = B[r][c] * sB[c]
__device__ float g_Aft[RANK * HIDDEN];
__device__ float g_Bf[RANK * HIDDEN];

// --- storage-format probe (validated R4+) ---
__device__ __forceinline__ int detect_mode(const void* p) {
    const unsigned* w = (const unsigned*)p;
    int vi = 0, vf = 0;
    #pragma unroll
    for (int i = 0; i < 32; i++) {
        unsigned u = w[i];
        int s = (int)u;
        if (s >= -127 && s <= 127) vi++;
        unsigned exp = (u >> 23) & 0xffu;
        if ((u & 0x7fffffffu) == 0u || (exp >= 127u && exp <= 133u)) vf++;
    }
    if (vi >= 24) return 1;
    if (vf >= 24) return 0;
    return 2;
}
__device__ __forceinline__ float load_elem(const void* p, int mode, int i) {
    if (mode == 1) return (float)((const int*)p)[i];
    if (mode == 0) return ((const float*)p)[i];
    return (float)((const signed char*)p)[i];
}

__global__ void prep_kernel(const void* __restrict__ A, const void* __restrict__ B,
                            const float* __restrict__ sA, const float* __restrict__ sB)
{
    __shared__ int mA, mB;
    if (threadIdx.x == 0) { mA = detect_mode(A); mB = detect_mode(B); }
    __syncthreads();
    const int i = blockIdx.x * blockDim.x + threadIdx.x;    // 65536 threads
    {
        const int k = i >> 4, r = i & 15;
        g_Aft[(size_t)r * HIDDEN + k] = load_elem(A, mA, i) * sA[r] * TWO_OVER_PI;
    }
    g_Bf[i] = load_elem(B, mB, i) * sB[i & (HIDDEN - 1)];
}

// sin(t): exact identity sin(t) = (-1)^q sin(t - q*pi); Cody-Waite 2-term pi;
// degree-9 odd minimax polynomial on |r| <= pi/2 (FMA pipe only).
__device__ __forceinline__ float fast_sin(float t) {
    const int qi = __float2int_rn(t * 0.3183098861837907f);
    const float q = (float)qi;
    float r = fmaf(q, -3.14159274101257f, t);
    r = fmaf(q, 8.742277657e-8f, r);
    r = (qi & 1) ? -r : r;
    const float s = r * r;
    float p = 2.86567956e-6f;
    p = fmaf(p, s, -1.98559923e-4f);
    p = fmaf(p, s,  8.33338592e-3f);
    p = fmaf(p, s, -1.66666672e-1f);
    return fmaf(p, r * s, r);
}

__global__ __launch_bounds__(THREADS, 1)       // 1 CTA/SM, 16 warps (same as R13)
void pilora_kernel(const float* __restrict__ x, float* __restrict__ y)
{
    extern __shared__ float xs[];              // [ROWS][HIDDEN]  128 KB
    __shared__ float red[NWARP][ROWS * (RANK / 2)];   // 16 x 64 floats = 4 KB
    __shared__ float hs[ROWS * RANK];          // 128 floats

    const int tid  = threadIdx.x;
    const int lane = tid & 31;
    const int w    = tid >> 5;
    const size_t rowbase = (size_t)blockIdx.x * ROWS;

    // ---- phase 1: two rank-half passes (weights read ONCE; x gmem on pass 0,
    // smem on pass 1). acc[8][8] = 64 regs keeps us spill-free at 512 thr. ----
    #pragma unroll
    for (int half = 0; half < 2; half++) {
        float acc[ROWS][RANK / 2];
        #pragma unroll
        for (int rr = 0; rr < ROWS; rr++)
            #pragma unroll
            for (int r = 0; r < RANK / 2; r++)
                acc[rr][r] = 0.0f;

        #pragma unroll
        for (int i = 0; i < 2; i++) {
            const int k0 = w * 256 + i * 128 + lane * 4;

            float4 xv[ROWS];
            if (half == 0) {
                #pragma unroll
                for (int rr = 0; rr < ROWS; rr++) {
                    xv[rr] = *(const float4*)(x + (rowbase + rr) * HIDDEN + k0);
                    *(float4*)(xs + rr * HIDDEN + k0) = xv[rr];   // warp-private stripe
                }
            } else {
                #pragma unroll
                for (int rr = 0; rr < ROWS; rr++)
                    xv[rr] = *(const float4*)(xs + rr * HIDDEN + k0);
            }

            // rank-chunked A loads: 4 independent LDG.128 in flight, then FMAs
            #pragma unroll
            for (int rc = 0; rc < 2; rc++) {
                float4 av[4];
                #pragma unroll
                for (int c = 0; c < 4; c++)
                    av[c] = *(const float4*)(g_Aft +
                              (size_t)(half * 8 + rc * 4 + c) * HIDDEN + k0);
                #pragma unroll
                for (int c = 0; c < 4; c++) {
                    const int r = rc * 4 + c;
                    #pragma unroll
                    for (int rr = 0; rr < ROWS; rr++) {
                        float t = acc[rr][r];
                        t = fmaf(xv[rr].x, av[c].x, t);
                        t = fmaf(xv[rr].y, av[c].y, t);
                        t = fmaf(xv[rr].z, av[c].z, t);
                        t = fmaf(xv[rr].w, av[c].w, t);
                        acc[rr][r] = t;
                    }
                }
            }
        }

        // warp butterfly reduction; lane 0 stores per-warp partials
        #pragma unroll
        for (int rr = 0; rr < ROWS; rr++) {
            #pragma unroll
            for (int r = 0; r < RANK / 2; r++) {
                float v = acc[rr][r];
                v += __shfl_xor_sync(0xffffffffu, v, 16);
                v += __shfl_xor_sync(0xffffffffu, v, 8);
                v += __shfl_xor_sync(0xffffffffu, v, 4);
                v += __shfl_xor_sync(0xffffffffu, v, 2);
                v += __shfl_xor_sync(0xffffffffu, v, 1);
                if (lane == 0) red[w][rr * (RANK / 2) + r] = v;
            }
        }
        __syncthreads();

        if (tid < ROWS * (RANK / 2)) {
            float h = 0.0f;
            #pragma unroll
            for (int ww = 0; ww < NWARP; ww++) h += red[ww][tid];
            const int rr = tid >> 3;           // tid / 8
            const int r  = tid & 7;
            hs[rr * RANK + half * 8 + r] = h;  // sA, 2/pi folded into Aft
        }
        __syncthreads();                        // red reused next half
    }

    // ---- phase 2: y = x + 2*sin( sum_r hs[row][r] * Bf[r][c] ) ----
    #pragma unroll
    for (int i = 0; i < 2; i++) {
        const int c0 = w * 256 + i * 128 + lane * 4;

        float acc2[ROWS][4];
        #pragma unroll
        for (int rr = 0; rr < ROWS; rr++)
            #pragma unroll
            for (int j = 0; j < 4; j++)
                acc2[rr][j] = 0.0f;

        // rank-chunked B loads: 4 independent LDG.128, then FMAs
        #pragma unroll
        for (int rc = 0; rc < 4; rc++) {
            float4 bv[4];
            #pragma unroll
            for (int c = 0; c < 4; c++)
                bv[c] = *(const float4*)(g_Bf + (size_t)(rc * 4 + c) * HIDDEN + c0);
            #pragma unroll
            for (int c = 0; c < 4; c++) {
                const int r = rc * 4 + c;
                #pragma unroll
                for (int rr = 0; rr < ROWS; rr++) {
                    const float hr = hs[rr * RANK + r];   // conflict-free broadcast
                    acc2[rr][0] = fmaf(hr, bv[c].x, acc2[rr][0]);
                    acc2[rr][1] = fmaf(hr, bv[c].y, acc2[rr][1]);
                    acc2[rr][2] = fmaf(hr, bv[c].z, acc2[rr][2]);
                    acc2[rr][3] = fmaf(hr, bv[c].w, acc2[rr][3]);
                }
            }
        }

        #pragma unroll
        for (int rr = 0; rr < ROWS; rr++) {
            const float4 xv = *(const float4*)(xs + rr * HIDDEN + c0);
            float4 ov;
            ov.x = fmaf(2.0f, fast_sin(acc2[rr][0]), xv.x);
            ov.y = fmaf(2.0f, fast_sin(acc2[rr][1]), xv.y);
            ov.z = fmaf(2.0f, fast_sin(acc2[rr][2]), xv.z);
            ov.w = fmaf(2.0f, fast_sin(acc2[rr][3]), xv.w);
            *(float4*)(y + (rowbase + rr) * HIDDEN + c0) = ov;
        }
    }
}

extern "C" void kernel_launch(void* const* d_in, const int* in_sizes, int n_in,
                              void* d_out, int out_size)
{
    // Rank-order binding by size (robust; validated since R4)
    int idx[16];
    const int m = (n_in < 16) ? n_in : 16;
    for (int i = 0; i < m; i++) idx[i] = i;
    for (int i = 0; i < m; i++) {
        int best = i;
        for (int j = i + 1; j < m; j++)
            if (in_sizes[idx[j]] < in_sizes[idx[best]]) best = j;
        if (best != i) {
            int t = idx[best];
            for (int j = best; j > i; j--) idx[j] = idx[j - 1];
            idx[i] = t;
        }
    }
    const float* sA = (const float*)d_in[idx[0]];
    const float* sB = (const float*)d_in[idx[1]];
    const void*  A  = d_in[idx[2]];
    const void*  B  = d_in[idx[3]];
    const float* x  = (const float*)d_in[idx[m - 1]];
    float* y = (float*)d_out;

    prep_kernel<<<(HIDDEN * RANK) / 256, 256>>>(A, B, sA, sB);

    const size_t smem = (size_t)ROWS * HIDDEN * sizeof(float);   // 128 KB
    cudaFuncSetAttribute(pilora_kernel,
                         cudaFuncAttributeMaxDynamicSharedMemorySize, (int)smem);
    pilora_kernel<<<TOTAL_ROWS / ROWS, THREADS, smem>>>(x, y);
}

// round 16
// speedup vs baseline: 2.0159x; 1.6631x over previous
#include <cuda_runtime.h>
#include <cstdint>

#define HIDDEN  4096
#define RANK    16
#define ROWS    4
#define THREADS 256
#define NWARP   8
#define TOTAL_ROWS 16384
#define TWO_OVER_PI 0.63661977236758134f

// Dequantized weights in device scratch (no allocations).
// g_Aft[r*HIDDEN+k] = A[k][r] * sA[r] * 2/pi   (transposed, coalesced loads)
// g_Bf [r*HIDDEN+c] = B[r][c] * sB[c]
__device__ float g_Aft[RANK * HIDDEN];
__device__ float g_Bf[RANK * HIDDEN];

// --- storage-format probe (validated R4+) ---
__device__ __forceinline__ int detect_mode(const void* p) {
    const unsigned* w = (const unsigned*)p;
    int vi = 0, vf = 0;
    #pragma unroll
    for (int i = 0; i < 32; i++) {
        unsigned u = w[i];
        int s = (int)u;
        if (s >= -127 && s <= 127) vi++;
        unsigned exp = (u >> 23) & 0xffu;
        if ((u & 0x7fffffffu) == 0u || (exp >= 127u && exp <= 133u)) vf++;
    }
    if (vi >= 24) return 1;
    if (vf >= 24) return 0;
    return 2;
}
__device__ __forceinline__ float load_elem(const void* p, int mode, int i) {
    if (mode == 1) return (float)((const int*)p)[i];
    if (mode == 0) return ((const float*)p)[i];
    return (float)((const signed char*)p)[i];
}

__global__ void prep_kernel(const void* __restrict__ A, const void* __restrict__ B,
                            const float* __restrict__ sA, const float* __restrict__ sB)
{
    __shared__ int mA, mB;
    if (threadIdx.x == 0) { mA = detect_mode(A); mB = detect_mode(B); }
    __syncthreads();
    const int i = blockIdx.x * blockDim.x + threadIdx.x;    // 65536 threads
    {
        const int k = i >> 4, r = i & 15;
        g_Aft[(size_t)r * HIDDEN + k] = load_elem(A, mA, i) * sA[r] * TWO_OVER_PI;
    }
    g_Bf[i] = load_elem(B, mB, i) * sB[i & (HIDDEN - 1)];
}

// sin(t): exact identity sin(t) = (-1)^q sin(t - q*pi); Cody-Waite 2-term pi;
// then a single MUFU sin on |r| <= pi/2 (HW-accurate on that range).
__device__ __forceinline__ float fast_sin(float t) {
    const int qi = __float2int_rn(t * 0.3183098861837907f);
    const float q = (float)qi;
    float r = fmaf(q, -3.14159274101257f, t);
    r = fmaf(q, 8.742277657e-8f, r);
    const float s = __sinf(r);                 // MUFU.SIN, |r| <= pi/2
    return (qi & 1) ? -s : s;
}

__global__ __launch_bounds__(THREADS, 2)          // 2 CTAs/SM
void pilora_kernel(const float* __restrict__ x, float* __restrict__ y)
{
    extern __shared__ float xs[];                 // [ROWS][HIDDEN]  64 KB
    __shared__ float red[NWARP][ROWS * RANK];
    __shared__ float hs[ROWS * RANK];

    const int tid  = threadIdx.x;
    const int lane = tid & 31;
    const int w    = tid >> 5;
    const size_t rowbase = (size_t)blockIdx.x * ROWS;

    // ---- phase 1 (fused staging + MLP-4 weight loads, as in R13) ----
    // Accumulators flattened: cur[v], v = rr*16 + r.
    float cur[ROWS * RANK];
    #pragma unroll
    for (int v = 0; v < ROWS * RANK; v++) cur[v] = 0.0f;

    #pragma unroll
    for (int i = 0; i < 4; i++) {
        const int k0 = w * 512 + i * 128 + lane * 4;

        float4 xv[ROWS];
        #pragma unroll
        for (int rr = 0; rr < ROWS; rr++) {
            xv[rr] = *(const float4*)(x + (rowbase + rr) * HIDDEN + k0);
            *(float4*)(xs + rr * HIDDEN + k0) = xv[rr];   // warp-private stripe
        }

        #pragma unroll
        for (int rc = 0; rc < 4; rc++) {
            float4 av[4];
            #pragma unroll
            for (int c = 0; c < 4; c++)
                av[c] = *(const float4*)(g_Aft + (size_t)(rc * 4 + c) * HIDDEN + k0);
            #pragma unroll
            for (int c = 0; c < 4; c++) {
                const int r = rc * 4 + c;
                #pragma unroll
                for (int rr = 0; rr < ROWS; rr++) {
                    float t = cur[rr * RANK + r];
                    t = fmaf(xv[rr].x, av[c].x, t);
                    t = fmaf(xv[rr].y, av[c].y, t);
                    t = fmaf(xv[rr].z, av[c].z, t);
                    t = fmaf(xv[rr].w, av[c].w, t);
                    cur[rr * RANK + r] = t;
                }
            }
        }
    }

    // ---- reduce-scatter butterfly: 5 stages, live set 64->32->16->8->4->2.
    // After stage s (offset 16>>s on lane bit), lane L's cur[0..E/2) holds the
    // warp-partials for a contiguous logical block selected by L's high bits.
    // End state: cur[0],cur[1] = fully warp-reduced h for v = 2L, 2L+1.
    #pragma unroll
    for (int s = 0; s < 5; s++) {
        const int E    = 64 >> s;          // live values before this stage
        const int half = E >> 1;
        const int off  = 16 >> s;
        const bool bit = (lane & off) != 0;
        #pragma unroll
        for (int j = 0; j < half; j++) {
            const float a = cur[j];
            const float b = cur[half + j];
            const float send = bit ? a : b;
            const float recv = __shfl_xor_sync(0xffffffffu, send, off);
            const float keep = bit ? b : a;
            cur[j] = keep + recv;
        }
    }
    // lane L owns v = 2L and 2L+1
    red[w][2 * lane]     = cur[0];
    red[w][2 * lane + 1] = cur[1];
    __syncthreads();

    if (tid < ROWS * RANK) {
        float h = 0.0f;
        #pragma unroll
        for (int ww = 0; ww < NWARP; ww++) h += red[ww][tid];
        hs[tid] = h;                       // sA and 2/pi already folded into Aft
    }
    __syncthreads();

    // ---- phase 2: y = x + 2*sin( sum_r hs[row][r] * Bf[r][c] ) ----
    #pragma unroll
    for (int i = 0; i < 4; i++) {
        const int c0 = w * 512 + i * 128 + lane * 4;

        float acc2[ROWS][4];
        #pragma unroll
        for (int rr = 0; rr < ROWS; rr++)
            #pragma unroll
            for (int j = 0; j < 4; j++)
                acc2[rr][j] = 0.0f;

        // rank-chunked B loads: 4 independent LDG.128, then 64 FMAs
        #pragma unroll
        for (int rc = 0; rc < 4; rc++) {
            float4 bv[4];
            #pragma unroll
            for (int c = 0; c < 4; c++)
                bv[c] = *(const float4*)(g_Bf + (size_t)(rc * 4 + c) * HIDDEN + c0);
            #pragma unroll
            for (int c = 0; c < 4; c++) {
                const int r = rc * 4 + c;
                #pragma unroll
                for (int rr = 0; rr < ROWS; rr++) {
                    const float hr = hs[rr * RANK + r];   // conflict-free broadcast
                    acc2[rr][0] = fmaf(hr, bv[c].x, acc2[rr][0]);
                    acc2[rr][1] = fmaf(hr, bv[c].y, acc2[rr][1]);
                    acc2[rr][2] = fmaf(hr, bv[c].z, acc2[rr][2]);
                    acc2[rr][3] = fmaf(hr, bv[c].w, acc2[rr][3]);
                }
            }
        }

        #pragma unroll
        for (int rr = 0; rr < ROWS; rr++) {
            const float4 xv = *(const float4*)(xs + rr * HIDDEN + c0);
            float4 ov;
            ov.x = fmaf(2.0f, fast_sin(acc2[rr][0]), xv.x);
            ov.y = fmaf(2.0f, fast_sin(acc2[rr][1]), xv.y);
            ov.z = fmaf(2.0f, fast_sin(acc2[rr][2]), xv.z);
            ov.w = fmaf(2.0f, fast_sin(acc2[rr][3]), xv.w);
            *(float4*)(y + (rowbase + rr) * HIDDEN + c0) = ov;
        }
    }
}

extern "C" void kernel_launch(void* const* d_in, const int* in_sizes, int n_in,
                              void* d_out, int out_size)
{
    // Rank-order binding by size (robust; validated since R4)
    int idx[16];
    const int m = (n_in < 16) ? n_in : 16;
    for (int i = 0; i < m; i++) idx[i] = i;
    for (int i = 0; i < m; i++) {
        int best = i;
        for (int j = i + 1; j < m; j++)
            if (in_sizes[idx[j]] < in_sizes[idx[best]]) best = j;
        if (best != i) {
            int t = idx[best];
            for (int j = best; j > i; j--) idx[j] = idx[j - 1];
            idx[i] = t;
        }
    }
    const float* sA = (const float*)d_in[idx[0]];
    const float* sB = (const float*)d_in[idx[1]];
    const void*  A  = d_in[idx[2]];
    const void*  B  = d_in[idx[3]];
    const float* x  = (const float*)d_in[idx[m - 1]];
    float* y = (float*)d_out;

    prep_kernel<<<(HIDDEN * RANK) / 256, 256>>>(A, B, sA, sB);

    const size_t smem = (size_t)ROWS * HIDDEN * sizeof(float);   // 64 KB
    cudaFuncSetAttribute(pilora_kernel,
                         cudaFuncAttributeMaxDynamicSharedMemorySize, (int)smem);
    pilora_kernel<<<TOTAL_ROWS / ROWS, THREADS, smem>>>(x, y);
}